// round 2
// baseline (speedup 1.0000x reference)
#include <cuda_runtime.h>
#include <stdint.h>

// InstantNGP hash-grid embedding.
// x: (B, 3) float32 in [-1, 1]
// embeddings: (16, 2^19, 2) float32
// out: (B, 32) float32  (levels concatenated, 2 feats each)

#define NLEV 16
#define TS   (1u << 19)
#define MSK  (TS - 1u)
#define P2   2654435761u
#define P3   805459861u

__global__ __launch_bounds__(256) void hashgrid_kernel(
    const float* __restrict__ x,
    const float* __restrict__ emb,
    float* __restrict__ out,
    int B)
{
    // res[i] = floor(16 * 2^(i/3)); function-scope constexpr so device code
    // can fold it at compile time under the unrolled loop.
    constexpr int RES_TBL[NLEV] = {16, 20, 25, 32, 40, 50, 64, 80,
                                   101, 128, 161, 203, 256, 322, 406, 512};

    const int i = blockIdx.x * blockDim.x + threadIdx.x;
    if (i >= B) return;

    const float x0 = x[3 * i + 0];
    const float x1 = x[3 * i + 1];
    const float x2 = x[3 * i + 2];

    // 32 output floats, kept in registers (level loop fully unrolled).
    float o[2 * NLEV];

    #pragma unroll
    for (int l = 0; l < NLEV; l++) {
        const int   res = RES_TBL[l];
        const float s   = 0.5f * (float)res;

        float r0 = (x0 + 1.0f) * s;
        float r1 = (x1 + 1.0f) * s;
        float r2 = (x2 + 1.0f) * s;

        float f0 = fminf(fmaxf(floorf(r0), 0.0f), (float)(res - 1));
        float f1 = fminf(fmaxf(floorf(r1), 0.0f), (float)(res - 1));
        float f2 = fminf(fmaxf(floorf(r2), 0.0f), (float)(res - 1));

        const float w0 = r0 - f0;
        const float w1 = r1 - f1;
        const float w2 = r2 - f2;
        const float v0 = 1.0f - w0;
        const float v1 = 1.0f - w1;
        const float v2 = 1.0f - w2;

        const uint32_t ix = (uint32_t)f0;
        const uint32_t iy = (uint32_t)f1;
        const uint32_t iz = (uint32_t)f2;

        // per-dim hash partial products for both corner values
        const uint32_t hx0 = ix;            // prime 1
        const uint32_t hx1 = ix + 1u;
        const uint32_t hy0 = iy * P2;
        const uint32_t hy1 = hy0 + P2;
        const uint32_t hz0 = iz * P3;
        const uint32_t hz1 = hz0 + P3;

        const float2* __restrict__ tbl =
            reinterpret_cast<const float2*>(emb) + (size_t)l * TS;

        float ax = 0.0f, ay = 0.0f;
        #pragma unroll
        for (int k = 0; k < 8; k++) {
            const uint32_t h = (((k & 1) ? hx1 : hx0) ^
                                ((k & 2) ? hy1 : hy0) ^
                                ((k & 4) ? hz1 : hz0)) & MSK;
            const float wt = ((k & 1) ? w0 : v0) *
                             ((k & 2) ? w1 : v1) *
                             ((k & 4) ? w2 : v2);
            const float2 vv = __ldg(tbl + h);
            ax = fmaf(wt, vv.x, ax);
            ay = fmaf(wt, vv.y, ay);
        }
        o[2 * l + 0] = ax;
        o[2 * l + 1] = ay;
    }

    // 8 x 16B contiguous stores per thread.
    float4* op = reinterpret_cast<float4*>(out + (size_t)i * (2 * NLEV));
    const float4* of = reinterpret_cast<const float4*>(o);
    #pragma unroll
    for (int j = 0; j < 8; j++) op[j] = of[j];
}

extern "C" void kernel_launch(void* const* d_in, const int* in_sizes, int n_in,
                              void* d_out, int out_size)
{
    const float* x   = (const float*)d_in[0];
    const float* emb = (const float*)d_in[1];
    float* out       = (float*)d_out;
    const int B      = in_sizes[0] / 3;

    const int threads = 256;
    const int blocks  = (B + threads - 1) / threads;
    hashgrid_kernel<<<blocks, threads>>>(x, emb, out, B);
}

// round 4
// speedup vs baseline: 1.1730x; 1.1730x over previous
#include <cuda_runtime.h>
#include <stdint.h>

// InstantNGP hash-grid embedding.
// x: (B, 3) float32 in [-1, 1]
// embeddings: (16, 2^19, 2) float32
// out: (B, 32) float32  (levels concatenated, 2 feats each)
//
// Key trick: x-dimension hash prime is 1, so for even ix the two x-corner
// hashes differ only in bit 0 -> adjacent table entries in one aligned 16B
// chunk -> fetch both corners with a single LDG.128 (4 gathers/level not 8).

#define NLEV 16
#define TS   (1u << 19)
#define MSK  (TS - 1u)
#define P2   2654435761u
#define P3   805459861u

__global__ __launch_bounds__(256) void hashgrid_kernel(
    const float* __restrict__ x,
    const float* __restrict__ emb,
    float* __restrict__ out,
    int B)
{
    constexpr int RES_TBL[NLEV] = {16, 20, 25, 32, 40, 50, 64, 80,
                                   101, 128, 161, 203, 256, 322, 406, 512};

    const int i = blockIdx.x * blockDim.x + threadIdx.x;
    if (i >= B) return;

    const float x0 = x[3 * i + 0];
    const float x1 = x[3 * i + 1];
    const float x2 = x[3 * i + 2];

    float o[2 * NLEV];   // 32 output floats, registers (level loop unrolled)

    #pragma unroll
    for (int l = 0; l < NLEV; l++) {
        const int   res = RES_TBL[l];
        const float s   = 0.5f * (float)res;

        const float r0 = (x0 + 1.0f) * s;
        const float r1 = (x1 + 1.0f) * s;
        const float r2 = (x2 + 1.0f) * s;

        const float f0 = fminf(fmaxf(floorf(r0), 0.0f), (float)(res - 1));
        const float f1 = fminf(fmaxf(floorf(r1), 0.0f), (float)(res - 1));
        const float f2 = fminf(fmaxf(floorf(r2), 0.0f), (float)(res - 1));

        const float w0 = r0 - f0, w1 = r1 - f1, w2 = r2 - f2;
        const float v0 = 1.0f - w0, v1 = 1.0f - w1, v2 = 1.0f - w2;

        const uint32_t ix = (uint32_t)f0;
        const uint32_t iy = (uint32_t)f1;
        const uint32_t iz = (uint32_t)f2;

        const uint32_t hy0 = iy * P2, hy1 = hy0 + P2;
        const uint32_t hz0 = iz * P3, hz1 = hz0 + P3;

        const float2* __restrict__ tbl =
            reinterpret_cast<const float2*>(emb) + (size_t)l * TS;

        float ax = 0.0f, ay = 0.0f;

        if ((ix & 1u) == 0u) {
            // Even ix: x-corner pair {h, h^1} lives in one aligned 16B chunk.
            const float4* __restrict__ tbl4 =
                reinterpret_cast<const float4*>(tbl);
            #pragma unroll
            for (int m = 0; m < 4; m++) {
                const uint32_t cyz = ((m & 1) ? hy1 : hy0) ^
                                     ((m & 2) ? hz1 : hz0);
                const float   wyz = ((m & 1) ? w1 : v1) *
                                    ((m & 2) ? w2 : v2);
                const uint32_t h0 = (ix ^ cyz) & MSK;      // x=0 corner
                const float wx0 = v0 * wyz;                // weight at h0
                const float wx1 = w0 * wyz;                // weight at h0^1
                // low entry of the pair = h0 & ~1
                const bool swp = (h0 & 1u) != 0u;
                const float wlo = swp ? wx1 : wx0;
                const float whi = swp ? wx0 : wx1;
                const float4 q = __ldg(tbl4 + (h0 >> 1));
                ax = fmaf(wlo, q.x, fmaf(whi, q.z, ax));
                ay = fmaf(wlo, q.y, fmaf(whi, q.w, ay));
            }
        } else {
            const uint32_t hx0 = ix, hx1 = ix + 1u;
            #pragma unroll
            for (int k = 0; k < 8; k++) {
                const uint32_t h = (((k & 1) ? hx1 : hx0) ^
                                    ((k & 2) ? hy1 : hy0) ^
                                    ((k & 4) ? hz1 : hz0)) & MSK;
                const float wt = ((k & 1) ? w0 : v0) *
                                 ((k & 2) ? w1 : v1) *
                                 ((k & 4) ? w2 : v2);
                const float2 vv = __ldg(tbl + h);
                ax = fmaf(wt, vv.x, ax);
                ay = fmaf(wt, vv.y, ay);
            }
        }
        o[2 * l + 0] = ax;
        o[2 * l + 1] = ay;
    }

    // 8 x 16B contiguous stores per thread.
    float4* op = reinterpret_cast<float4*>(out + (size_t)i * (2 * NLEV));
    const float4* of = reinterpret_cast<const float4*>(o);
    #pragma unroll
    for (int j = 0; j < 8; j++) op[j] = of[j];
}

extern "C" void kernel_launch(void* const* d_in, const int* in_sizes, int n_in,
                              void* d_out, int out_size)
{
    const float* x   = (const float*)d_in[0];
    const float* emb = (const float*)d_in[1];
    float* out       = (float*)d_out;
    const int B      = in_sizes[0] / 3;

    const int threads = 256;
    const int blocks  = (B + threads - 1) / threads;
    hashgrid_kernel<<<blocks, threads>>>(x, emb, out, B);
}